// round 1
// baseline (speedup 1.0000x reference)
#include <cuda_runtime.h>
#include <cuda_bf16.h>
#include <math.h>

#define S_LEN 4096
#define D_MOD 768
#define N_HEAD 12
#define DH 64
#define N_LAYER 4
#define FF_DIM 3072
#define CHUNK 256
#define WIN 256

// ---------------- scratch (device globals; no allocation) ----------------
__device__ float g_x [S_LEN * D_MOD];
__device__ float g_q [S_LEN * D_MOD];
__device__ float g_k [S_LEN * D_MOD];
__device__ float g_v [S_LEN * D_MOD];
__device__ float g_a [S_LEN * D_MOD];
__device__ float g_o [S_LEN * D_MOD];
__device__ float g_ff[S_LEN * FF_DIM];
__device__ float g_pooled[D_MOD];
__device__ float g_h1[512];
__device__ float g_h2[256];
__device__ float g_msum[1];

// ---------------- embedding ----------------
__global__ void embed_kernel(const int* __restrict__ ids,
                             const float* __restrict__ wemb,
                             const float* __restrict__ pemb,
                             float* __restrict__ X)
{
    int row = blockIdx.x;
    int id  = ids[row];
    const float* wp = wemb + (size_t)id * D_MOD;
    const float* pp = pemb + (size_t)row * D_MOD;
    float* xp = X + (size_t)row * D_MOD;
    for (int d = threadIdx.x; d < D_MOD; d += blockDim.x)
        xp[d] = wp[d] + pp[d];
}

// ---------------- LayerNorm (optionally with residual add), in-place on X ----
__global__ void __launch_bounds__(256) ln_kernel(float* __restrict__ X,
                                                 const float* __restrict__ Aadd,
                                                 const float* __restrict__ g,
                                                 const float* __restrict__ b)
{
    int row = blockIdx.x;
    int tid = threadIdx.x;
    __shared__ float red[256];
    float vals[3];
    float s = 0.f;
    const size_t base = (size_t)row * D_MOD;
#pragma unroll
    for (int i = 0; i < 3; i++) {
        int d = tid + i * 256;
        float v = X[base + d];
        if (Aadd) v += Aadd[base + d];
        vals[i] = v;
        s += v;
    }
    red[tid] = s; __syncthreads();
    for (int o = 128; o > 0; o >>= 1) { if (tid < o) red[tid] += red[tid + o]; __syncthreads(); }
    float mean = red[0] * (1.0f / D_MOD);
    __syncthreads();
    float ss = 0.f;
#pragma unroll
    for (int i = 0; i < 3; i++) { float dv = vals[i] - mean; ss += dv * dv; }
    red[tid] = ss; __syncthreads();
    for (int o = 128; o > 0; o >>= 1) { if (tid < o) red[tid] += red[tid + o]; __syncthreads(); }
    float rstd = rsqrtf(red[0] * (1.0f / D_MOD) + 1e-5f);
#pragma unroll
    for (int i = 0; i < 3; i++) {
        int d = tid + i * 256;
        X[base + d] = (vals[i] - mean) * rstd * g[d] + b[d];
    }
}

// ---------------- SGEMM 128x128x8, fp32, fused epilogue ----------------
// EPI: 0 = bias, 1 = bias then *0.125 (Q scale), 2 = bias then exact GELU
template<int EPI>
__global__ void __launch_bounds__(256) sgemm_kernel(const float* __restrict__ A,
                                                    const float* __restrict__ B,
                                                    const float* __restrict__ bias,
                                                    float* __restrict__ C,
                                                    int M, int N, int K)
{
    __shared__ float As[8][128];
    __shared__ float Bs[8][128];
    int tid = threadIdx.x;
    int m0 = blockIdx.y * 128;
    int n0 = blockIdx.x * 128;
    int tx = tid & 15, ty = tid >> 4;

    float acc[8][8];
#pragma unroll
    for (int i = 0; i < 8; i++)
#pragma unroll
        for (int j = 0; j < 8; j++) acc[i][j] = 0.f;

    int a_row = tid >> 1;
    int a_k4  = (tid & 1) * 4;
    int b_k   = tid >> 5;
    int b_n4  = (tid & 31) * 4;

    const float* Aptr = A + (size_t)(m0 + a_row) * K + a_k4;
    const float* Bptr = B + (size_t)b_k * N + n0 + b_n4;

    for (int k0 = 0; k0 < K; k0 += 8) {
        float4 av = *(const float4*)(Aptr + k0);
        As[a_k4 + 0][a_row] = av.x;
        As[a_k4 + 1][a_row] = av.y;
        As[a_k4 + 2][a_row] = av.z;
        As[a_k4 + 3][a_row] = av.w;
        *(float4*)&Bs[b_k][b_n4] = *(const float4*)(Bptr + (size_t)k0 * N);
        __syncthreads();
#pragma unroll
        for (int kk = 0; kk < 8; kk++) {
            float a_frag[8], b_frag[8];
#pragma unroll
            for (int i = 0; i < 8; i++) a_frag[i] = As[kk][ty * 8 + i];
#pragma unroll
            for (int j = 0; j < 8; j++) b_frag[j] = Bs[kk][tx * 8 + j];
#pragma unroll
            for (int i = 0; i < 8; i++)
#pragma unroll
                for (int j = 0; j < 8; j++)
                    acc[i][j] += a_frag[i] * b_frag[j];
        }
        __syncthreads();
    }

#pragma unroll
    for (int i = 0; i < 8; i++) {
        int row = m0 + ty * 8 + i;
#pragma unroll
        for (int j = 0; j < 8; j++) {
            int col = n0 + tx * 8 + j;
            float v = acc[i][j] + bias[col];
            if (EPI == 1) v *= 0.125f;
            if (EPI == 2) v = 0.5f * v * (1.0f + erff(v * 0.70710678118654752f));
            C[(size_t)row * N + col] = v;
        }
    }
}

// ---------------- band attention (flash-style online softmax) ----------------
__global__ void __launch_bounds__(256) attn_kernel(const float* __restrict__ Q,
                                                   const float* __restrict__ K,
                                                   const float* __restrict__ V,
                                                   const int* __restrict__ mask,
                                                   float* __restrict__ O)
{
    int n  = blockIdx.x;   // chunk 0..15
    int h  = blockIdx.y;   // head 0..11
    int qi = threadIdx.x;  // query row in chunk
    int sq = n * CHUNK + qi;

    __shared__ float ks[64][64];
    __shared__ float vs[64][64];

    float qreg[64];
    const float* qp = Q + (size_t)sq * D_MOD + h * DH;
#pragma unroll
    for (int d = 0; d < 64; d++) qreg[d] = qp[d];

    float m = -1e30f, l = 0.f;
    float acc[64];
#pragma unroll
    for (int d = 0; d < 64; d++) acc[d] = 0.f;

    int lo = sq - WIN; if (lo < 0) lo = 0;
    int hi = sq + WIN; if (hi > S_LEN - 1) hi = S_LEN - 1;
    int base = n * CHUNK - CHUNK;
    // block-uniform union of key range
    int blo = base;            if (blo < 0) blo = 0;
    int bhi = base + 3 * CHUNK - 1 + WIN - WIN; // [base, base+767]
    bhi = base + 767;          if (bhi > S_LEN - 1) bhi = S_LEN - 1;

    for (int t = 0; t < 12; t++) {
        int tstart = base + t * 64;
        if (tstart + 63 < blo || tstart > bhi) continue;   // block-uniform skip
        __syncthreads();
        for (int e = threadIdx.x; e < 64 * 64; e += 256) {
            int jj = e >> 6, d = e & 63;
            int g2 = tstart + jj;
            float kv = 0.f, vv = 0.f;
            if (g2 >= 0 && g2 < S_LEN) {
                size_t off = (size_t)g2 * D_MOD + h * DH + d;
                kv = K[off];
                vv = V[off];
            }
            ks[jj][d] = kv;
            vs[jj][d] = vv;
        }
        __syncthreads();
        int j0 = lo - tstart; if (j0 < 0) j0 = 0;
        int j1 = hi - tstart; if (j1 > 63) j1 = 63;
        for (int jj = j0; jj <= j1; jj++) {
            int g2 = tstart + jj;
            if (mask[g2] == 0) continue;
            float s = 0.f;
#pragma unroll
            for (int d = 0; d < 64; d++) s += qreg[d] * ks[jj][d];
            if (s <= m) {
                float p = __expf(s - m);
                l += p;
#pragma unroll
                for (int d = 0; d < 64; d++) acc[d] += p * vs[jj][d];
            } else {
                float sc = __expf(m - s);
                l = l * sc + 1.0f;
#pragma unroll
                for (int d = 0; d < 64; d++) acc[d] = acc[d] * sc + vs[jj][d];
                m = s;
            }
        }
    }
    float inv = 1.0f / l;
    float* op = O + (size_t)sq * D_MOD + h * DH;
#pragma unroll
    for (int d = 0; d < 64; d++) op[d] = acc[d] * inv;
}

// ---------------- pooling + head ----------------
__global__ void zero_pooled_kernel(float* __restrict__ pooled)
{
    for (int d = threadIdx.x; d < D_MOD; d += blockDim.x) pooled[d] = 0.f;
}

__global__ void msum_kernel(const int* __restrict__ mask, float* __restrict__ out)
{
    __shared__ float red[256];
    int tid = threadIdx.x;
    float s = 0.f;
    for (int i = tid; i < S_LEN; i += 256) s += (float)mask[i];
    red[tid] = s; __syncthreads();
    for (int o = 128; o > 0; o >>= 1) { if (tid < o) red[tid] += red[tid + o]; __syncthreads(); }
    if (tid == 0) out[0] = fmaxf(red[0], 1e-9f);
}

__global__ void __launch_bounds__(256) pool_kernel(const float* __restrict__ X,
                                                   const int* __restrict__ mask,
                                                   float* __restrict__ pooled)
{
    int s0 = blockIdx.x * 256;
    int tid = threadIdx.x;
    float a0 = 0.f, a1 = 0.f, a2 = 0.f;
    for (int r = 0; r < 256; r++) {
        float mf = (float)mask[s0 + r];
        const float* xp = X + (size_t)(s0 + r) * D_MOD;
        a0 += xp[tid]       * mf;
        a1 += xp[tid + 256] * mf;
        a2 += xp[tid + 512] * mf;
    }
    atomicAdd(&pooled[tid],       a0);
    atomicAdd(&pooled[tid + 256], a1);
    atomicAdd(&pooled[tid + 512], a2);
}

__global__ void head1_kernel(const float* __restrict__ pooled,
                             const float* __restrict__ W1, const float* __restrict__ b1,
                             const float* __restrict__ msum, float* __restrict__ h1)
{
    int i = threadIdx.x;   // 512 threads
    float inv = 1.0f / msum[0];
    float dot = 0.f;
    for (int d = 0; d < D_MOD; d++) dot += pooled[d] * W1[(size_t)d * 512 + i];
    h1[i] = fmaxf(dot * inv + b1[i], 0.f);
}

__global__ void head2_kernel(const float* __restrict__ h1,
                             const float* __restrict__ W2, const float* __restrict__ b2,
                             float* __restrict__ h2)
{
    int i = threadIdx.x;   // 256 threads
    if (i < 250) {
        float dot = 0.f;
        for (int d = 0; d < 512; d++) dot += h1[d] * W2[(size_t)d * 250 + i];
        h2[i] = fmaxf(dot + b2[i], 0.f);
    } else if (i < 256) {
        h2[i] = 0.f;
    }
}

__global__ void head3_kernel(const float* __restrict__ h2,
                             const float* __restrict__ W3, const float* __restrict__ b3,
                             float* __restrict__ out, int out_size)
{
    __shared__ float red[256];
    __shared__ float pred;
    int tid = threadIdx.x;
    float v = (tid < 250) ? h2[tid] * W3[tid] : 0.f;
    red[tid] = v; __syncthreads();
    for (int o = 128; o > 0; o >>= 1) { if (tid < o) red[tid] += red[tid + o]; __syncthreads(); }
    if (tid == 0) pred = red[0] + b3[0];
    __syncthreads();
    for (int i = tid; i < out_size; i += 256) out[i] = pred;
}

// ---------------- launch ----------------
extern "C" void kernel_launch(void* const* d_in, const int* in_sizes, int n_in,
                              void* d_out, int out_size)
{
    const int*   ids    = (const int*)  d_in[0];
    const int*   mask   = (const int*)  d_in[1];
    const float* wemb   = (const float*)d_in[2];
    const float* pemb   = (const float*)d_in[3];
    const float* emb_g  = (const float*)d_in[4];
    const float* emb_b  = (const float*)d_in[5];
    const float* Wq     = (const float*)d_in[6];
    const float* Wk     = (const float*)d_in[7];
    const float* Wv     = (const float*)d_in[8];
    const float* Wo     = (const float*)d_in[9];
    const float* bq     = (const float*)d_in[10];
    const float* bk     = (const float*)d_in[11];
    const float* bv     = (const float*)d_in[12];
    const float* bo     = (const float*)d_in[13];
    const float* ln1_g  = (const float*)d_in[14];
    const float* ln1_b  = (const float*)d_in[15];
    const float* Wff1   = (const float*)d_in[16];
    const float* bff1   = (const float*)d_in[17];
    const float* Wff2   = (const float*)d_in[18];
    const float* bff2   = (const float*)d_in[19];
    const float* ln2_g  = (const float*)d_in[20];
    const float* ln2_b  = (const float*)d_in[21];
    const float* W1     = (const float*)d_in[22];
    const float* b1     = (const float*)d_in[23];
    const float* W2     = (const float*)d_in[24];
    const float* b2     = (const float*)d_in[25];
    const float* W3     = (const float*)d_in[26];
    const float* b3     = (const float*)d_in[27];
    float* out = (float*)d_out;

    float *x, *q, *k, *v, *a, *o, *ff, *pooled, *h1, *h2, *msum;
    cudaGetSymbolAddress((void**)&x,      g_x);
    cudaGetSymbolAddress((void**)&q,      g_q);
    cudaGetSymbolAddress((void**)&k,      g_k);
    cudaGetSymbolAddress((void**)&v,      g_v);
    cudaGetSymbolAddress((void**)&a,      g_a);
    cudaGetSymbolAddress((void**)&o,      g_o);
    cudaGetSymbolAddress((void**)&ff,     g_ff);
    cudaGetSymbolAddress((void**)&pooled, g_pooled);
    cudaGetSymbolAddress((void**)&h1,     g_h1);
    cudaGetSymbolAddress((void**)&h2,     g_h2);
    cudaGetSymbolAddress((void**)&msum,   g_msum);

    dim3 gemm_blk(256);
    dim3 g768 (D_MOD / 128, S_LEN / 128);   // (6, 32)
    dim3 g3072(FF_DIM / 128, S_LEN / 128);  // (24, 32)

    embed_kernel<<<S_LEN, 256>>>(ids, wemb, pemb, x);
    ln_kernel<<<S_LEN, 256>>>(x, nullptr, emb_g, emb_b);

    for (int l = 0; l < N_LAYER; l++) {
        const float* Wq_l  = Wq  + (size_t)l * D_MOD * D_MOD;
        const float* Wk_l  = Wk  + (size_t)l * D_MOD * D_MOD;
        const float* Wv_l  = Wv  + (size_t)l * D_MOD * D_MOD;
        const float* Wo_l  = Wo  + (size_t)l * D_MOD * D_MOD;
        const float* Wf1_l = Wff1 + (size_t)l * D_MOD * FF_DIM;
        const float* Wf2_l = Wff2 + (size_t)l * FF_DIM * D_MOD;

        sgemm_kernel<1><<<g768, gemm_blk>>>(x, Wq_l, bq + l * D_MOD, q, S_LEN, D_MOD, D_MOD);
        sgemm_kernel<0><<<g768, gemm_blk>>>(x, Wk_l, bk + l * D_MOD, k, S_LEN, D_MOD, D_MOD);
        sgemm_kernel<0><<<g768, gemm_blk>>>(x, Wv_l, bv + l * D_MOD, v, S_LEN, D_MOD, D_MOD);

        attn_kernel<<<dim3(S_LEN / CHUNK, N_HEAD), 256>>>(q, k, v, mask, a);

        sgemm_kernel<0><<<g768, gemm_blk>>>(a, Wo_l, bo + l * D_MOD, o, S_LEN, D_MOD, D_MOD);
        ln_kernel<<<S_LEN, 256>>>(x, o, ln1_g + l * D_MOD, ln1_b + l * D_MOD);

        sgemm_kernel<2><<<g3072, gemm_blk>>>(x, Wf1_l, bff1 + l * FF_DIM, ff, S_LEN, FF_DIM, D_MOD);
        sgemm_kernel<0><<<g768,  gemm_blk>>>(ff, Wf2_l, bff2 + l * D_MOD, o, S_LEN, D_MOD, FF_DIM);
        ln_kernel<<<S_LEN, 256>>>(x, o, ln2_g + l * D_MOD, ln2_b + l * D_MOD);
    }

    zero_pooled_kernel<<<1, 256>>>(pooled);
    msum_kernel<<<1, 256>>>(mask, msum);
    pool_kernel<<<S_LEN / 256, 256>>>(x, mask, pooled);
    head1_kernel<<<1, 512>>>(pooled, W1, b1, msum, h1);
    head2_kernel<<<1, 256>>>(h1, W2, b2, h2);
    head3_kernel<<<1, 256>>>(h2, W3, b3, out, out_size);
}